// round 6
// baseline (speedup 1.0000x reference)
#include <cuda_runtime.h>
#include <cstdint>
#include <cstddef>

// ---------------------------------------------------------------------------
// Problem: 20 independent GEMMs (block-diagonal ensemble linear)
//   x:   [32768, 4000] f32
//   W:   [2000, 4000]  f32
//   out: [32768, 2000] f32
//   block n: out[:, n*100:(n+1)*100] =
//            x[:, n*200:(n+1)*200] @ W[n*100:(n+1)*100, n*200:(n+1)*200]^T
//
// Implementation: tf32 mma.sync.m16n8k8 (legacy HMMA path, works on plain
// sm_100 target — tcgen05 is unavailable because the harness PTX target lacks
// the 'a' suffix). cp.async double-buffered K-chunk pipeline.
// ---------------------------------------------------------------------------

static constexpr int BATCH   = 32768;
static constexpr int NUM     = 20;
static constexpr int IN_SZ   = 200;               // K per block
static constexpr int OUT_SZ  = 100;               // N per block (real)
static constexpr int X_LD    = NUM * IN_SZ;       // 4000
static constexpr int W_LD    = NUM * IN_SZ;       // 4000
static constexpr int OUT_LD  = NUM * OUT_SZ;      // 2000

static constexpr int M_TILE  = 256;               // CTA M tile
static constexpr int N_TILE  = 112;               // CTA N tile (padded 100->112)
static constexpr int KC      = 40;                // K chunk
static constexpr int NCHUNK  = IN_SZ / KC;        // 5
static constexpr int STR     = 44;                // smem row stride (floats), conflict-free

static constexpr int A_ELEMS = M_TILE * STR;      // 11264 floats per buffer
static constexpr int B_ELEMS = N_TILE * STR;      // 4928  floats per buffer
static constexpr int SMEM_FLOATS = 2 * A_ELEMS + 2 * B_ELEMS;       // 32384
static constexpr int SMEM_BYTES  = SMEM_FLOATS * 4;                 // 129536

static constexpr int THREADS = 256;               // 8 warps: 4 (M) x 2 (N)
// warp tile: 64 (M) x 56 (N) -> 4 m16 tiles x 7 n8 tiles per k8 step

// ---------------------------------------------------------------------------
// PTX helpers
// ---------------------------------------------------------------------------
__device__ __forceinline__ uint32_t smem_u32(const void* p) {
    uint32_t a;
    asm("{ .reg .u64 t; cvta.to.shared.u64 t, %1; cvt.u32.u64 %0, t; }"
        : "=r"(a) : "l"(p));
    return a;
}

__device__ __forceinline__ void cp16(uint32_t dst, const float* src) {
    asm volatile("cp.async.cg.shared.global [%0], [%1], 16;"
                 :: "r"(dst), "l"(src));
}

#define CP_COMMIT() asm volatile("cp.async.commit_group;" ::: "memory")
#define CP_WAIT(n)  asm volatile("cp.async.wait_group %0;" :: "n"(n) : "memory")

__device__ __forceinline__ uint32_t f2tf32(float f) {
    uint32_t r;
    asm("cvt.rna.tf32.f32 %0, %1;" : "=r"(r) : "f"(f));
    return r;
}

// D(16x8,f32) += A(16x8,tf32) * B(8x8,tf32);  A row-major, B col-major (K contiguous)
__device__ __forceinline__ void mma_tf32(float c[4],
                                         uint32_t a0, uint32_t a1, uint32_t a2, uint32_t a3,
                                         uint32_t b0, uint32_t b1) {
    asm volatile(
        "mma.sync.aligned.m16n8k8.row.col.f32.tf32.tf32.f32 "
        "{%0,%1,%2,%3}, {%4,%5,%6,%7}, {%8,%9}, {%0,%1,%2,%3};"
        : "+f"(c[0]), "+f"(c[1]), "+f"(c[2]), "+f"(c[3])
        : "r"(a0), "r"(a1), "r"(a2), "r"(a3), "r"(b0), "r"(b1));
}

// ---------------------------------------------------------------------------
// Kernel: one CTA = (M=256 batch tile) x (one ensemble block n)
// ---------------------------------------------------------------------------
__global__ void __launch_bounds__(THREADS, 1)
ensemble_linear_mma_kernel(const float* __restrict__ x,
                           const float* __restrict__ W,
                           float* __restrict__ out) {
    extern __shared__ float smem[];
    float* Asm = smem;                       // [2][256*44]
    float* Bsm = smem + 2 * A_ELEMS;         // [2][112*44]
    const uint32_t a_base = smem_u32(Asm);
    const uint32_t b_base = smem_u32(Bsm);

    const int tid = threadIdx.x;
    const int wid = tid >> 5;
    const int lid = tid & 31;
    const int g   = lid >> 2;     // group id 0..7
    const int tg  = lid & 3;      // thread-in-group 0..3
    const int wm  = wid >> 1;     // 0..3  (M direction)
    const int wn  = wid & 1;      // 0..1  (N direction)

    const int n  = blockIdx.x;    // ensemble block 0..19
    const int mt = blockIdx.y;    // M tile 0..127

    // Zero B padding rows 100..111 in both buffers (never written by cp.async)
    {
        // 2 bufs * 12 rows * STR floats = 1056
        for (int i = tid; i < 2 * 12 * STR; i += THREADS) {
            int s   = i / (12 * STR);
            int rem = i - s * (12 * STR);
            int r   = 100 + rem / STR;
            int c   = rem - (rem / STR) * STR;
            Bsm[s * B_ELEMS + r * STR + c] = 0.0f;
        }
    }

    // Global base pointers for this CTA
    const float* xbase = x + (size_t)mt * M_TILE * X_LD + (size_t)n * IN_SZ;
    const float* wbase = W + (size_t)n * OUT_SZ * W_LD + (size_t)n * IN_SZ;

    // ---- chunk loader (cp.async, 16B ops) ----------------------------------
    auto load_chunk = [&](int c, int s) {
        const float* xs = xbase + c * KC;
        const uint32_t adst = a_base + (uint32_t)(s * A_ELEMS) * 4u;
        // A: 256 rows x 10 float4 = 2560 ops -> 10 per thread
        #pragma unroll
        for (int j = 0; j < 10; ++j) {
            int idx = tid + j * THREADS;
            int r = idx / 10;
            int i = idx - r * 10;
            cp16(adst + (uint32_t)(r * STR + i * 4) * 4u,
                 xs + (size_t)r * X_LD + i * 4);
        }
        const float* ws = wbase + c * KC;
        const uint32_t bdst = b_base + (uint32_t)(s * B_ELEMS) * 4u;
        // B: 100 rows x 10 float4 = 1000 ops
        #pragma unroll
        for (int j = 0; j < 4; ++j) {
            int idx = tid + j * THREADS;
            if (idx < OUT_SZ * 10) {
                int r = idx / 10;
                int i = idx - r * 10;
                cp16(bdst + (uint32_t)(r * STR + i * 4) * 4u,
                     ws + (size_t)r * W_LD + i * 4);
            }
        }
    };

    // Accumulators: 4 m16 tiles x 7 n8 tiles x 4 regs
    float acc[4][7][4];
    #pragma unroll
    for (int t = 0; t < 4; ++t)
        #pragma unroll
        for (int j = 0; j < 7; ++j)
            #pragma unroll
            for (int q = 0; q < 4; ++q)
                acc[t][j][q] = 0.0f;

    // ---- pipelined mainloop -------------------------------------------------
    load_chunk(0, 0);
    CP_COMMIT();

    #pragma unroll
    for (int c = 0; c < NCHUNK; ++c) {
        if (c + 1 < NCHUNK) {
            load_chunk(c + 1, (c + 1) & 1);
            CP_COMMIT();
            CP_WAIT(1);                      // chunk c resident
        } else {
            CP_WAIT(0);
        }
        __syncthreads();

        const float* Ab = Asm + (c & 1) * A_ELEMS;
        const float* Bb = Bsm + (c & 1) * B_ELEMS;

        #pragma unroll
        for (int ks = 0; ks < KC / 8; ++ks) {   // 5 k8-steps
            const int k0 = ks * 8;

            uint32_t a[4][4];
            #pragma unroll
            for (int t = 0; t < 4; ++t) {
                const float* ap = Ab + (wm * 64 + t * 16 + g) * STR + k0 + tg;
                a[t][0] = f2tf32(ap[0]);
                a[t][1] = f2tf32(ap[8 * STR]);
                a[t][2] = f2tf32(ap[4]);
                a[t][3] = f2tf32(ap[8 * STR + 4]);
            }
            uint32_t b[7][2];
            #pragma unroll
            for (int j = 0; j < 7; ++j) {
                const float* bp = Bb + (wn * 56 + j * 8 + g) * STR + k0 + tg;
                b[j][0] = f2tf32(bp[0]);
                b[j][1] = f2tf32(bp[4]);
            }
            #pragma unroll
            for (int t = 0; t < 4; ++t)
                #pragma unroll
                for (int j = 0; j < 7; ++j)
                    mma_tf32(acc[t][j], a[t][0], a[t][1], a[t][2], a[t][3],
                             b[j][0], b[j][1]);
        }
        __syncthreads();   // buffer (c&1) may be refilled next iteration
    }

    // ---- epilogue: register accumulators -> global --------------------------
    const int row_base = mt * M_TILE + wm * 64;
    #pragma unroll
    for (int t = 0; t < 4; ++t) {
        const int r0 = row_base + t * 16 + g;
        float* orow = out + (size_t)r0 * OUT_LD + (size_t)n * OUT_SZ;
        #pragma unroll
        for (int j = 0; j < 7; ++j) {
            const int cgl = wn * 56 + j * 8 + 2 * tg;   // 0..110, even
            if (cgl < OUT_SZ) {
                float2 v0 = make_float2(acc[t][j][0], acc[t][j][1]);
                float2 v1 = make_float2(acc[t][j][2], acc[t][j][3]);
                *(float2*)(orow + cgl)                     = v0;   // row r0
                *(float2*)(orow + (size_t)8 * OUT_LD + cgl) = v1;  // row r0+8
            }
        }
    }
}

// ---------------------------------------------------------------------------
// Launch
// ---------------------------------------------------------------------------
extern "C" void kernel_launch(void* const* d_in, const int* in_sizes, int n_in,
                              void* d_out, int out_size) {
    const float* x = (const float*)d_in[0];   // [32768, 4000]
    const float* W = (const float*)d_in[1];   // [2000, 4000]
    float* out = (float*)d_out;               // [32768, 2000]

    static bool attr_set = false;
    if (!attr_set) {
        cudaFuncSetAttribute(ensemble_linear_mma_kernel,
                             cudaFuncAttributeMaxDynamicSharedMemorySize,
                             SMEM_BYTES);
        attr_set = true;
    }

    dim3 grid(NUM, BATCH / M_TILE, 1);        // 20 x 128 = 2560 CTAs
    ensemble_linear_mma_kernel<<<grid, THREADS, SMEM_BYTES>>>(x, W, out);
}

// round 7
// speedup vs baseline: 1.0081x; 1.0081x over previous
#include <cuda_runtime.h>
#include <cstdint>
#include <cstddef>

// ---------------------------------------------------------------------------
// Problem: 20 independent GEMMs (block-diagonal ensemble linear)
//   x:   [32768, 4000] f32
//   W:   [2000, 4000]  f32
//   out: [32768, 2000] f32
//   block n: out[:, n*100:(n+1)*100] =
//            x[:, n*200:(n+1)*200] @ W[n*100:(n+1)*100, n*200:(n+1)*200]^T
//
// tf32 mma.sync.m16n8k8 + cp.async double-buffered pipeline.
// R7 change: M_TILE 256->128 so regs<=128 and smem<=82.5KB -> 2 CTAs/SM
// (16 warps resident, cross-CTA latency hiding).
// ---------------------------------------------------------------------------

static constexpr int BATCH   = 32768;
static constexpr int NUM     = 20;
static constexpr int IN_SZ   = 200;               // K per block
static constexpr int OUT_SZ  = 100;               // N per block (real)
static constexpr int X_LD    = NUM * IN_SZ;       // 4000
static constexpr int W_LD    = NUM * IN_SZ;       // 4000
static constexpr int OUT_LD  = NUM * OUT_SZ;      // 2000

static constexpr int M_TILE  = 128;               // CTA M tile
static constexpr int N_TILE  = 112;               // CTA N tile (padded 100->112)
static constexpr int KC      = 40;                // K chunk
static constexpr int NCHUNK  = IN_SZ / KC;        // 5
static constexpr int STR     = 44;                // smem row stride (floats), conflict-free

static constexpr int A_ELEMS = M_TILE * STR;      // 5632 floats per buffer
static constexpr int B_ELEMS = N_TILE * STR;      // 4928 floats per buffer
static constexpr int SMEM_FLOATS = 2 * A_ELEMS + 2 * B_ELEMS;   // 21120
static constexpr int SMEM_BYTES  = SMEM_FLOATS * 4;             // 84480

static constexpr int THREADS = 256;               // 8 warps: 4 (M) x 2 (N)
// warp tile: 32 (M) x 56 (N) -> 2 m16 tiles x 7 n8 tiles per k8 step

// ---------------------------------------------------------------------------
// PTX helpers
// ---------------------------------------------------------------------------
__device__ __forceinline__ uint32_t smem_u32(const void* p) {
    uint32_t a;
    asm("{ .reg .u64 t; cvta.to.shared.u64 t, %1; cvt.u32.u64 %0, t; }"
        : "=r"(a) : "l"(p));
    return a;
}

__device__ __forceinline__ void cp16(uint32_t dst, const float* src) {
    asm volatile("cp.async.cg.shared.global [%0], [%1], 16;"
                 :: "r"(dst), "l"(src));
}

#define CP_COMMIT() asm volatile("cp.async.commit_group;" ::: "memory")
#define CP_WAIT(n)  asm volatile("cp.async.wait_group %0;" :: "n"(n) : "memory")

__device__ __forceinline__ uint32_t f2tf32(float f) {
    uint32_t r;
    asm("cvt.rna.tf32.f32 %0, %1;" : "=r"(r) : "f"(f));
    return r;
}

// D(16x8,f32) += A(16x8,tf32) * B(8x8,tf32);  A row-major, B col-major (K contiguous)
__device__ __forceinline__ void mma_tf32(float c[4],
                                         uint32_t a0, uint32_t a1, uint32_t a2, uint32_t a3,
                                         uint32_t b0, uint32_t b1) {
    asm volatile(
        "mma.sync.aligned.m16n8k8.row.col.f32.tf32.tf32.f32 "
        "{%0,%1,%2,%3}, {%4,%5,%6,%7}, {%8,%9}, {%0,%1,%2,%3};"
        : "+f"(c[0]), "+f"(c[1]), "+f"(c[2]), "+f"(c[3])
        : "r"(a0), "r"(a1), "r"(a2), "r"(a3), "r"(b0), "r"(b1));
}

// ---------------------------------------------------------------------------
// Kernel: one CTA = (M=128 batch tile) x (one ensemble block n), 2 CTAs/SM
// ---------------------------------------------------------------------------
__global__ void __launch_bounds__(THREADS, 2)
ensemble_linear_mma_kernel(const float* __restrict__ x,
                           const float* __restrict__ W,
                           float* __restrict__ out) {
    extern __shared__ float smem[];
    float* Asm = smem;                       // [2][128*44]
    float* Bsm = smem + 2 * A_ELEMS;         // [2][112*44]
    const uint32_t a_base = smem_u32(Asm);
    const uint32_t b_base = smem_u32(Bsm);

    const int tid = threadIdx.x;
    const int wid = tid >> 5;
    const int lid = tid & 31;
    const int g   = lid >> 2;     // group id 0..7
    const int tg  = lid & 3;      // thread-in-group 0..3
    const int wm  = wid >> 1;     // 0..3  (M direction)
    const int wn  = wid & 1;      // 0..1  (N direction)

    const int n  = blockIdx.x;    // ensemble block 0..19
    const int mt = blockIdx.y;    // M tile 0..255

    // Zero B padding rows 100..111 in both buffers (never written by cp.async)
    for (int i = tid; i < 2 * 12 * STR; i += THREADS) {
        int s   = i / (12 * STR);
        int rem = i - s * (12 * STR);
        int r   = 100 + rem / STR;
        int c   = rem - (rem / STR) * STR;
        Bsm[s * B_ELEMS + r * STR + c] = 0.0f;
    }

    // Global base pointers for this CTA
    const float* xbase = x + (size_t)mt * M_TILE * X_LD + (size_t)n * IN_SZ;
    const float* wbase = W + (size_t)n * OUT_SZ * W_LD + (size_t)n * IN_SZ;

    // ---- chunk loader (cp.async, 16B ops) ----------------------------------
    auto load_chunk = [&](int c, int s) {
        const float* xs = xbase + c * KC;
        const uint32_t adst = a_base + (uint32_t)(s * A_ELEMS) * 4u;
        // A: 128 rows x 10 float4 = 1280 ops -> 5 per thread
        #pragma unroll
        for (int j = 0; j < 5; ++j) {
            int idx = tid + j * THREADS;
            int r = idx / 10;
            int i = idx - r * 10;
            cp16(adst + (uint32_t)(r * STR + i * 4) * 4u,
                 xs + (size_t)r * X_LD + i * 4);
        }
        const float* ws = wbase + c * KC;
        const uint32_t bdst = b_base + (uint32_t)(s * B_ELEMS) * 4u;
        // B: 100 rows x 10 float4 = 1000 ops
        #pragma unroll
        for (int j = 0; j < 4; ++j) {
            int idx = tid + j * THREADS;
            if (idx < OUT_SZ * 10) {
                int r = idx / 10;
                int i = idx - r * 10;
                cp16(bdst + (uint32_t)(r * STR + i * 4) * 4u,
                     ws + (size_t)r * W_LD + i * 4);
            }
        }
    };

    // Accumulators: 2 m16 tiles x 7 n8 tiles x 4 regs = 56 floats
    float acc[2][7][4];
    #pragma unroll
    for (int t = 0; t < 2; ++t)
        #pragma unroll
        for (int j = 0; j < 7; ++j)
            #pragma unroll
            for (int q = 0; q < 4; ++q)
                acc[t][j][q] = 0.0f;

    // ---- pipelined mainloop -------------------------------------------------
    load_chunk(0, 0);
    CP_COMMIT();

    #pragma unroll
    for (int c = 0; c < NCHUNK; ++c) {
        if (c + 1 < NCHUNK) {
            load_chunk(c + 1, (c + 1) & 1);
            CP_COMMIT();
            CP_WAIT(1);                      // chunk c resident
        } else {
            CP_WAIT(0);
        }
        __syncthreads();

        const float* Ab = Asm + (c & 1) * A_ELEMS;
        const float* Bb = Bsm + (c & 1) * B_ELEMS;

        #pragma unroll
        for (int ks = 0; ks < KC / 8; ++ks) {   // 5 k8-steps
            const int k0 = ks * 8;

            uint32_t a[2][4];
            #pragma unroll
            for (int t = 0; t < 2; ++t) {
                const float* ap = Ab + (wm * 32 + t * 16 + g) * STR + k0 + tg;
                a[t][0] = f2tf32(ap[0]);
                a[t][1] = f2tf32(ap[8 * STR]);
                a[t][2] = f2tf32(ap[4]);
                a[t][3] = f2tf32(ap[8 * STR + 4]);
            }
            uint32_t b[7][2];
            #pragma unroll
            for (int j = 0; j < 7; ++j) {
                const float* bp = Bb + (wn * 56 + j * 8 + g) * STR + k0 + tg;
                b[j][0] = f2tf32(bp[0]);
                b[j][1] = f2tf32(bp[4]);
            }
            #pragma unroll
            for (int t = 0; t < 2; ++t)
                #pragma unroll
                for (int j = 0; j < 7; ++j)
                    mma_tf32(acc[t][j], a[t][0], a[t][1], a[t][2], a[t][3],
                             b[j][0], b[j][1]);
        }
        __syncthreads();   // buffer (c&1) may be refilled next iteration
    }

    // ---- epilogue: register accumulators -> global --------------------------
    const int row_base = mt * M_TILE + wm * 32;
    #pragma unroll
    for (int t = 0; t < 2; ++t) {
        const int r0 = row_base + t * 16 + g;
        float* orow = out + (size_t)r0 * OUT_LD + (size_t)n * OUT_SZ;
        #pragma unroll
        for (int j = 0; j < 7; ++j) {
            const int cgl = wn * 56 + j * 8 + 2 * tg;   // 0..110, even
            if (cgl < OUT_SZ) {
                float2 v0 = make_float2(acc[t][j][0], acc[t][j][1]);
                float2 v1 = make_float2(acc[t][j][2], acc[t][j][3]);
                *(float2*)(orow + cgl)                      = v0;  // row r0
                *(float2*)(orow + (size_t)8 * OUT_LD + cgl) = v1;  // row r0+8
            }
        }
    }
}

// ---------------------------------------------------------------------------
// Launch
// ---------------------------------------------------------------------------
extern "C" void kernel_launch(void* const* d_in, const int* in_sizes, int n_in,
                              void* d_out, int out_size) {
    const float* x = (const float*)d_in[0];   // [32768, 4000]
    const float* W = (const float*)d_in[1];   // [2000, 4000]
    float* out = (float*)d_out;               // [32768, 2000]

    static bool attr_set = false;
    if (!attr_set) {
        cudaFuncSetAttribute(ensemble_linear_mma_kernel,
                             cudaFuncAttributeMaxDynamicSharedMemorySize,
                             SMEM_BYTES);
        attr_set = true;
    }

    dim3 grid(NUM, BATCH / M_TILE, 1);        // 20 x 256 = 5120 CTAs
    ensemble_linear_mma_kernel<<<grid, THREADS, SMEM_BYTES>>>(x, W, out);
}